// round 1
// baseline (speedup 1.0000x reference)
#include <cuda_runtime.h>
#include <cstdint>

#define B_  32
#define K_  17
#define H_  192
#define W_  192
#define C_  19
#define P_  20
#define S_  10
#define HW_ (H_*W_)

#define PEAK_THRESH      0.1f
#define PAF_SCORE_THRESH 0.05f
#define PAF_COUNT_THRESH 0.8f

#define CAND_CAP 12288
#define NT1      256

__constant__ int SKEL_A[C_] = {15,13,16,14,11, 5, 6, 5, 5, 6, 7, 8, 1, 0, 0, 1, 2, 3, 4};
__constant__ int SKEL_B[C_] = {13,11,14,12,12,11,12, 6, 7, 8, 9,10, 2, 1, 2, 3, 4, 5, 6};

// ---------------------------------------------------------------------------
// Kernel 1: per (b,k) channel — 3x3 local-max peaks, top-20 by (score desc,
// pixel index asc), subpixel refinement, write peaks (B,K,P,3) to out.
// ---------------------------------------------------------------------------
__global__ __launch_bounds__(NT1)
void peaks_kernel(const float* __restrict__ heat, float* __restrict__ out_peaks)
{
    const int bk = blockIdx.x;                 // 0 .. B*K-1
    const float* __restrict__ h = heat + (size_t)bk * HW_;

    extern __shared__ float smem[];
    float* c_score = smem;                             // CAND_CAP floats
    int*   c_idx   = (int*)(smem + CAND_CAP);          // CAND_CAP ints

    __shared__ int  s_count;
    __shared__ unsigned long long w_key[NT1/32];
    __shared__ int  w_slot[NT1/32];
    __shared__ int   sel_pix[P_];
    __shared__ float sel_sc[P_];

    const int tid = threadIdx.x;
    if (tid == 0) s_count = 0;
    __syncthreads();

    // ---- Phase 1: candidate collection ----
    for (int p = tid; p < HW_; p += NT1) {
        float v = h[p];
        if (v <= PEAK_THRESH) continue;
        int y = p / W_;
        int x = p - y * W_;

        // strict "equals 3x3 window max" test == v >= all valid neighbors
        bool pk = true;
        // same row
        if (x > 0      && v < h[p - 1])       pk = false;
        if (pk && x < W_-1 && v < h[p + 1])   pk = false;
        if (pk && y > 0) {
            const float* r = h + p - W_;
            if (v < r[0]) pk = false;
            if (pk && x > 0      && v < r[-1]) pk = false;
            if (pk && x < W_-1   && v < r[ 1]) pk = false;
        }
        if (pk && y < H_-1) {
            const float* r = h + p + W_;
            if (v < r[0]) pk = false;
            if (pk && x > 0      && v < r[-1]) pk = false;
            if (pk && x < W_-1   && v < r[ 1]) pk = false;
        }
        if (pk) {
            int slot = atomicAdd(&s_count, 1);
            if (slot < CAND_CAP) { c_score[slot] = v; c_idx[slot] = p; }
        }
    }
    __syncthreads();
    const int nc = min(s_count, CAND_CAP);

    // ---- Phase 2: 20 rounds of block argmax (top_k semantics) ----
    for (int r = 0; r < P_; r++) {
        unsigned long long bkey = 0ull;
        int bslot = -1;
        for (int i = tid; i < nc; i += NT1) {
            float sc = c_score[i];
            if (sc > 0.0f) {
                unsigned long long key =
                    ((unsigned long long)__float_as_uint(sc) << 32) |
                    (unsigned)(0xFFFFFFFFu - (unsigned)c_idx[i]);
                if (key > bkey) { bkey = key; bslot = i; }
            }
        }
        // warp reduce
        #pragma unroll
        for (int o = 16; o > 0; o >>= 1) {
            unsigned long long ok = __shfl_down_sync(0xffffffffu, bkey, o);
            int os = __shfl_down_sync(0xffffffffu, bslot, o);
            if (ok > bkey) { bkey = ok; bslot = os; }
        }
        if ((tid & 31) == 0) { w_key[tid >> 5] = bkey; w_slot[tid >> 5] = bslot; }
        __syncthreads();
        if (tid == 0) {
            unsigned long long best = 0ull; int bsl = -1;
            #pragma unroll
            for (int w = 0; w < NT1/32; w++)
                if (w_key[w] > best) { best = w_key[w]; bsl = w_slot[w]; }
            if (bsl >= 0) {
                sel_pix[r] = c_idx[bsl];
                sel_sc[r]  = c_score[bsl];
                c_score[bsl] = 0.0f;         // invalidate
            } else {
                sel_pix[r] = -1;
                sel_sc[r]  = -1.0f;
            }
        }
        __syncthreads();
    }

    // ---- Phase 3: subpixel refine + write ----
    if (tid < P_) {
        float sc = sel_sc[tid];
        float px = 0.0f, py = 0.0f, so = 0.0f;
        if (sc > PEAK_THRESH) {
            int p = sel_pix[tid];
            int y = p / W_;
            int x = p - y * W_;
            float ddx = 0.0f, ddy = 0.0f;
            if (x > 0 && x < W_-1 && y > 0 && y < H_-1) {
                float c = h[p];
                float rr = h[p + 1], ll = h[p - 1];
                float dd = h[p + W_], uu = h[p - W_];
                float dx  = 0.5f * (rr - ll);
                float dxx = (rr + ll) - 2.0f * c;
                if (dxx != 0.0f) dx = dx / (-dxx);
                float dy  = 0.5f * (dd - uu);
                float dyy = (dd + uu) - 2.0f * c;
                if (dyy != 0.0f) dy = dy / (-dyy);
                ddx = dx; ddy = dy;
            }
            px = (float)x + ddx;
            py = (float)y + ddy;
            so = sc;
        }
        float* o = out_peaks + ((size_t)bk * P_ + tid) * 3;
        o[0] = px; o[1] = py; o[2] = so;
    }
}

// ---------------------------------------------------------------------------
// Kernel 2: per (b,c) edge — PAF line-integral scoring over P x P peak pairs.
// ---------------------------------------------------------------------------
#define NT2 128
__global__ __launch_bounds__(NT2)
void conn_kernel(const float* __restrict__ paf,
                 const float* __restrict__ peaks,
                 float* __restrict__ conn)
{
    const int c = blockIdx.x;   // 0..C_-1
    const int b = blockIdx.y;   // 0..B_-1

    __shared__ float ax[P_], ay[P_], sa[P_];
    __shared__ float bx[P_], by[P_], sb[P_];

    const int tid = threadIdx.x;
    if (tid < 2 * P_) {
        int j = (tid < P_) ? tid : tid - P_;
        int joint = (tid < P_) ? SKEL_A[c] : SKEL_B[c];
        const float* pk = peaks + (((size_t)b * K_ + joint) * P_ + j) * 3;
        float x = pk[0], y = pk[1], s = pk[2];
        if (tid < P_) { ax[j] = x; ay[j] = y; sa[j] = s; }
        else          { bx[j] = x; by[j] = y; sb[j] = s; }
    }
    __syncthreads();

    const float* __restrict__ pafx = paf + ((size_t)b * (2*C_) + 2*c) * HW_;
    const float* __restrict__ pafy = pafx + HW_;

    const float delta = 1.0f / 9.0f;   // fp32-rounded linspace step

    for (int cell = tid; cell < P_*P_; cell += NT2) {
        int i = cell / P_;   // A peak index
        int j = cell - i * P_;

        float axi = ax[i], ayi = ay[i];
        float dxl = bx[j] - axi;
        float dyl = by[j] - ayi;
        float norm = sqrtf(dxl*dxl + dyl*dyl) + 1e-8f;
        float vx = dxl / norm, vy = dyl / norm;

        float cnt = 0.0f, sum = 0.0f, cntp = 0.0f;
        #pragma unroll
        for (int s = 0; s < S_; s++) {
            float t = (s == S_-1) ? 1.0f : (float)s * delta;
            float xs = axi + dxl * t;
            float ys = ayi + dyl * t;
            int xi = __float2int_rz(xs);   // truncate toward zero (astype int32)
            int yi = __float2int_rz(ys);
            bool inb = (xi >= 0) & (xi < W_) & (yi >= 0) & (yi < H_);
            if (inb) {
                int idx = yi * W_ + xi;    // in-bounds, no clip needed
                float pxv = pafx[idx];
                float pyv = pafy[idx];
                float vs = pxv * vx + pyv * vy;
                cnt  += 1.0f;
                sum  += vs;
                if (vs > PAF_SCORE_THRESH) cntp += 1.0f;
            }
        }
        float denom = fmaxf(cnt, 1.0f);
        float mean  = sum / denom;
        float ratio = cntp / denom;
        bool ok = (cnt > 0.0f) && (mean > 0.0f) && (ratio > PAF_COUNT_THRESH)
                  && (sa[i] > PEAK_THRESH) && (sb[j] > PEAK_THRESH);
        float val = ok ? (mean + 0.5f * (sa[i] + sb[j])) : 0.0f;
        conn[(((size_t)b * C_ + c) * P_ + i) * P_ + j] = val;
    }
}

// ---------------------------------------------------------------------------
extern "C" void kernel_launch(void* const* d_in, const int* in_sizes, int n_in,
                              void* d_out, int out_size)
{
    const float* heat = (const float*)d_in[0];
    const float* paf  = (const float*)d_in[1];
    // defensive: swap if the harness ordered inputs by size differently
    if (n_in >= 2 && in_sizes[0] == B_ * 2 * C_ * HW_ && in_sizes[1] == B_ * K_ * HW_) {
        heat = (const float*)d_in[1];
        paf  = (const float*)d_in[0];
    }

    float* out_peaks = (float*)d_out;                      // B*K*P*3
    float* out_conn  = out_peaks + (size_t)B_ * K_ * P_ * 3;

    const int dyn_smem = CAND_CAP * 8;  // 96 KB candidate list
    cudaFuncSetAttribute(peaks_kernel,
                         cudaFuncAttributeMaxDynamicSharedMemorySize, dyn_smem);

    peaks_kernel<<<B_ * K_, NT1, dyn_smem>>>(heat, out_peaks);

    dim3 g2(C_, B_);
    conn_kernel<<<g2, NT2>>>(paf, out_peaks, out_conn);
}

// round 2
// speedup vs baseline: 2.3079x; 2.3079x over previous
#include <cuda_runtime.h>
#include <cstdint>
#include <cfloat>

#define B_  32
#define K_  17
#define H_  192
#define W_  192
#define C_  19
#define P_  20
#define S_  10
#define HW_ (H_*W_)

#define PEAK_THRESH      0.1f
#define PAF_SCORE_THRESH 0.05f
#define PAF_COUNT_THRESH 0.8f

#define NT1      256
#define TROWS    16
#define TILE_R   (TROWS + 2)
#define NTILES   (H_ / TROWS)
#define CAND_CAP 5120
#define SURV_CAP 512
#define NBINS    256

__constant__ int SKEL_A[C_] = {15,13,16,14,11, 5, 6, 5, 5, 6, 7, 8, 1, 0, 0, 1, 2, 3, 4};
__constant__ int SKEL_B[C_] = {13,11,14,12,12,11,12, 6, 7, 8, 9,10, 2, 1, 2, 3, 4, 5, 6};

__device__ __forceinline__ float fmax3(float a, float b, float c) {
    return fmaxf(a, fmaxf(b, c));
}

// ---------------------------------------------------------------------------
// Kernel 1: per (b,k) channel. Branchless tiled 3x3 local-max + histogram
// top-20 selection + subpixel refinement. Writes peaks (B,K,P,3).
// ---------------------------------------------------------------------------
__global__ __launch_bounds__(NT1)
void peaks_kernel(const float* __restrict__ heat, float* __restrict__ out_peaks)
{
    const int bk = blockIdx.x;
    const float* __restrict__ h = heat + (size_t)bk * HW_;

    __shared__ float vt[TILE_R][W_];   // staged rows
    __shared__ float hm[TILE_R][W_];   // horizontal 3-max per row
    __shared__ int   hist[NBINS];
    __shared__ int   s_count;
    __shared__ int   s_nsurv;
    __shared__ int   s_tbin;
    __shared__ unsigned long long w_key[NT1/32];
    __shared__ int   w_slot[NT1/32];
    __shared__ unsigned long long sel_key[P_];

    extern __shared__ unsigned long long dynsm[];
    unsigned long long* keys = dynsm;              // CAND_CAP
    unsigned long long* surv = dynsm + CAND_CAP;   // SURV_CAP

    const int tid  = threadIdx.x;
    const int lane = tid & 31;
    const int wid  = tid >> 5;

    if (tid < NBINS) hist[tid] = 0;
    if (tid == 0) { s_count = 0; s_nsurv = 0; }
    __syncthreads();

    // ================= Phase 1: candidate collection =================
    for (int tile = 0; tile < NTILES; tile++) {
        const int ybase = tile * TROWS;
        __syncthreads();   // protect vt/hm from previous tile's readers

        // --- load 18 rows (ybase-1 .. ybase+16) as float4 ---
        for (int i = tid; i < TILE_R * (W_/4); i += NT1) {
            int r  = i / (W_/4);
            int g  = i - r * (W_/4);
            int gy = ybase - 1 + r;
            float4 val;
            if (gy >= 0 && gy < H_)
                val = __ldg((const float4*)(h + (size_t)gy * W_) + g);
            else
                val = make_float4(-FLT_MAX, -FLT_MAX, -FLT_MAX, -FLT_MAX);
            *(float4*)&vt[r][g*4] = val;
        }
        __syncthreads();

        // --- horizontal 3-max ---
        for (int i = tid; i < TILE_R * (W_/4); i += NT1) {
            int r = i / (W_/4);
            int g = i - r * (W_/4);
            float4 c = *(const float4*)&vt[r][g*4];
            float left  = (g > 0)        ? vt[r][g*4 - 1] : -FLT_MAX;
            float right = (g < W_/4 - 1) ? vt[r][g*4 + 4] : -FLT_MAX;
            float4 o;
            o.x = fmax3(left, c.x, c.y);
            o.y = fmax3(c.x, c.y, c.z);
            o.z = fmax3(c.y, c.z, c.w);
            o.w = fmax3(c.z, c.w, right);
            *(float4*)&hm[r][g*4] = o;
        }
        __syncthreads();

        // --- peak test (uniform trip count: 16*48/256 = 3) ---
        for (int i = tid; i < TROWS * (W_/4); i += NT1) {
            int gy = i / (W_/4);
            int g  = i - gy * (W_/4);
            int ty = gy + 1;

            float4 v  = *(const float4*)&vt[ty][g*4];
            float4 m0 = *(const float4*)&hm[ty-1][g*4];
            float4 m1 = *(const float4*)&hm[ty  ][g*4];
            float4 m2 = *(const float4*)&hm[ty+1][g*4];

            float vv[4] = {v.x, v.y, v.z, v.w};
            float mm[4] = {fmax3(m0.x, m1.x, m2.x), fmax3(m0.y, m1.y, m2.y),
                           fmax3(m0.z, m1.z, m2.z), fmax3(m0.w, m1.w, m2.w)};

            unsigned long long lkey[4];
            int lbin[4];
            int cnt = 0;
            const int prow = (ybase + gy) * W_ + g * 4;
            #pragma unroll
            for (int c = 0; c < 4; c++) {
                if (vv[c] > PEAK_THRESH && vv[c] >= mm[c]) {
                    int p = prow + c;
                    lkey[cnt] = ((unsigned long long)__float_as_uint(vv[c]) << 32)
                              | (unsigned)(0xFFFFFFFFu - (unsigned)p);
                    lbin[cnt] = min(NBINS - 1, (int)(vv[c] * (float)NBINS));
                    cnt++;
                }
            }
            // warp-aggregated append
            int off = cnt;
            #pragma unroll
            for (int d = 1; d < 32; d <<= 1) {
                int n = __shfl_up_sync(0xffffffffu, off, d);
                if (lane >= d) off += n;
            }
            int total = __shfl_sync(0xffffffffu, off, 31);
            int excl  = off - cnt;
            int base = 0;
            if (lane == 31 && total > 0) base = atomicAdd(&s_count, total);
            base = __shfl_sync(0xffffffffu, base, 31);
            for (int c = 0; c < cnt; c++) {
                int pos = base + excl + c;
                if (pos < CAND_CAP) {
                    keys[pos] = lkey[c];
                    atomicAdd(&hist[lbin[c]], 1);
                }
            }
        }
    }
    __syncthreads();

    const int nc = min(s_count, CAND_CAP);

    // ================= Phase 2: histogram-guided top-20 =================
    if (tid == 0) {
        int need = min(P_, nc);
        int cum = 0, t = 0;
        if (need > 0) {
            for (int b = NBINS - 1; b >= 0; --b) {
                cum += hist[b];
                if (cum >= need) { t = b; break; }
            }
        }
        s_tbin = t;
    }
    __syncthreads();
    const int tbin = s_tbin;

    for (int i = tid; i < nc; i += NT1) {
        unsigned long long k = keys[i];
        float sc = __uint_as_float((unsigned)(k >> 32));
        int bin = min(NBINS - 1, (int)(sc * (float)NBINS));
        if (bin >= tbin) {
            int slot = atomicAdd(&s_nsurv, 1);
            if (slot < SURV_CAP) surv[slot] = k;
        }
    }
    __syncthreads();

    unsigned long long* list;
    int len;
    if (s_nsurv <= SURV_CAP) { list = surv; len = s_nsurv; }
    else                     { list = keys; len = nc; }   // rare fallback

    // exact 20-round argmax (top_k semantics: score desc, index asc)
    for (int r = 0; r < P_; r++) {
        unsigned long long bkey = 0ull;
        int bslot = -1;
        for (int i = tid; i < len; i += NT1) {
            unsigned long long k = list[i];
            if (k > bkey) { bkey = k; bslot = i; }
        }
        #pragma unroll
        for (int o = 16; o > 0; o >>= 1) {
            unsigned long long ok = __shfl_down_sync(0xffffffffu, bkey, o);
            int os = __shfl_down_sync(0xffffffffu, bslot, o);
            if (ok > bkey) { bkey = ok; bslot = os; }
        }
        if (lane == 0) { w_key[wid] = bkey; w_slot[wid] = bslot; }
        __syncthreads();
        if (tid == 0) {
            unsigned long long best = 0ull; int bsl = -1;
            #pragma unroll
            for (int w = 0; w < NT1/32; w++)
                if (w_key[w] > best) { best = w_key[w]; bsl = w_slot[w]; }
            sel_key[r] = best;
            if (bsl >= 0) list[bsl] = 0ull;
        }
        __syncthreads();
    }

    // ================= Phase 3: subpixel refine + write =================
    if (tid < P_) {
        unsigned long long k = sel_key[tid];
        float px = 0.0f, py = 0.0f, so = 0.0f;
        if (k != 0ull) {
            float sc = __uint_as_float((unsigned)(k >> 32));
            int p = (int)(0xFFFFFFFFu - (unsigned)(k & 0xFFFFFFFFull));
            int y = p / W_;
            int x = p - y * W_;
            float ddx = 0.0f, ddy = 0.0f;
            if (x > 0 && x < W_-1 && y > 0 && y < H_-1) {
                float c  = h[p];
                float rr = h[p + 1],  ll = h[p - 1];
                float dd = h[p + W_], uu = h[p - W_];
                float dx  = 0.5f * (rr - ll);
                float dxx = (rr + ll) - 2.0f * c;
                if (dxx != 0.0f) dx = dx / (-dxx);
                float dy  = 0.5f * (dd - uu);
                float dyy = (dd + uu) - 2.0f * c;
                if (dyy != 0.0f) dy = dy / (-dyy);
                ddx = dx; ddy = dy;
            }
            px = (float)x + ddx;
            py = (float)y + ddy;
            so = sc;
        }
        float* o = out_peaks + ((size_t)bk * P_ + tid) * 3;
        o[0] = px; o[1] = py; o[2] = so;
    }
}

// ---------------------------------------------------------------------------
// Kernel 2: per (b,c) edge — PAF line-integral scoring, one thread per cell,
// unconditional clamped gathers for full MLP.
// ---------------------------------------------------------------------------
#define NT2 416
__global__ __launch_bounds__(NT2)
void conn_kernel(const float* __restrict__ paf,
                 const float* __restrict__ peaks,
                 float* __restrict__ conn)
{
    const int c = blockIdx.x;
    const int b = blockIdx.y;

    __shared__ float ax[P_], ay[P_], sa[P_];
    __shared__ float bx[P_], by[P_], sb[P_];

    const int tid = threadIdx.x;
    if (tid < 2 * P_) {
        int j = (tid < P_) ? tid : tid - P_;
        int joint = (tid < P_) ? SKEL_A[c] : SKEL_B[c];
        const float* pk = peaks + (((size_t)b * K_ + joint) * P_ + j) * 3;
        float x = pk[0], y = pk[1], s = pk[2];
        if (tid < P_) { ax[j] = x; ay[j] = y; sa[j] = s; }
        else          { bx[j] = x; by[j] = y; sb[j] = s; }
    }
    __syncthreads();

    if (tid >= P_ * P_) return;

    const float* __restrict__ pafx = paf + ((size_t)b * (2*C_) + 2*c) * HW_;
    const float* __restrict__ pafy = pafx + HW_;

    const float delta = 1.0f / 9.0f;

    const int i = tid / P_;
    const int j = tid - i * P_;

    float axi = ax[i], ayi = ay[i];
    float dxl = bx[j] - axi;
    float dyl = by[j] - ayi;
    float norm = sqrtf(dxl*dxl + dyl*dyl) + 1e-8f;
    float vx = dxl / norm, vy = dyl / norm;

    int   idx[S_];
    bool  inb[S_];
    #pragma unroll
    for (int s = 0; s < S_; s++) {
        float t = (s == S_-1) ? 1.0f : (float)s * delta;
        float xs = axi + dxl * t;
        float ys = ayi + dyl * t;
        int xi = __float2int_rz(xs);
        int yi = __float2int_rz(ys);
        inb[s] = (xi >= 0) & (xi < W_) & (yi >= 0) & (yi < H_);
        int xc = min(max(xi, 0), W_ - 1);
        int yc = min(max(yi, 0), H_ - 1);
        idx[s] = yc * W_ + xc;
    }

    float pxv[S_], pyv[S_];
    #pragma unroll
    for (int s = 0; s < S_; s++) pxv[s] = __ldg(pafx + idx[s]);
    #pragma unroll
    for (int s = 0; s < S_; s++) pyv[s] = __ldg(pafy + idx[s]);

    float cnt = 0.0f, sum = 0.0f, cntp = 0.0f;
    #pragma unroll
    for (int s = 0; s < S_; s++) {
        float vs = pxv[s] * vx + pyv[s] * vy;
        if (inb[s]) {
            cnt += 1.0f;
            sum += vs;
            if (vs > PAF_SCORE_THRESH) cntp += 1.0f;
        }
    }

    float denom = fmaxf(cnt, 1.0f);
    float mean  = sum / denom;
    float ratio = cntp / denom;
    bool ok = (cnt > 0.0f) && (mean > 0.0f) && (ratio > PAF_COUNT_THRESH)
              && (sa[i] > PEAK_THRESH) && (sb[j] > PEAK_THRESH);
    float val = ok ? (mean + 0.5f * (sa[i] + sb[j])) : 0.0f;
    conn[(((size_t)b * C_ + c) * P_ + i) * P_ + j] = val;
}

// ---------------------------------------------------------------------------
extern "C" void kernel_launch(void* const* d_in, const int* in_sizes, int n_in,
                              void* d_out, int out_size)
{
    const float* heat = (const float*)d_in[0];
    const float* paf  = (const float*)d_in[1];
    if (n_in >= 2 && in_sizes[0] == B_ * 2 * C_ * HW_ && in_sizes[1] == B_ * K_ * HW_) {
        heat = (const float*)d_in[1];
        paf  = (const float*)d_in[0];
    }

    float* out_peaks = (float*)d_out;                      // B*K*P*3
    float* out_conn  = out_peaks + (size_t)B_ * K_ * P_ * 3;

    const int dyn_smem = (CAND_CAP + SURV_CAP) * 8;        // 45 KB
    cudaFuncSetAttribute(peaks_kernel,
                         cudaFuncAttributeMaxDynamicSharedMemorySize, dyn_smem);

    peaks_kernel<<<B_ * K_, NT1, dyn_smem>>>(heat, out_peaks);

    dim3 g2(C_, B_);
    conn_kernel<<<g2, NT2>>>(paf, out_peaks, out_conn);
}